// round 1
// baseline (speedup 1.0000x reference)
#include <cuda_runtime.h>

// QConv2d: new_rho[b] = V * rho[b] * V^T, with V = uc[:,2:4] (x) ux (x) uy
// (Kronecker structure; channel insertion maps index x -> x+128, so only the
// bottom-right 128x128 block of rho_big is nonzero and V = U[:,128:256]).
// Computed via in-place mode products in one shared-memory tile per batch:
//   step1: contract col j-mode with uy      (cols, contiguous groups of 8)
//   step2: contract col i-mode with ux      (cols, stride-8 groups)
//   step3: contract row j-mode with uy      (rows, contiguous groups of 8)
//   step4: contract row i-mode with ux      (rows, stride-8 groups)
//   step5: expand channel modes with uc[:,2:4] on both sides -> gmem
// Each step's 8-element groups are thread-private => in-place is safe; only
// inter-step __syncthreads needed. One 128x132 f32 buffer = 67.6 KB smem,
// 2 blocks/SM => all 256 batches in one wave.

#define SROW 132

__global__ __launch_bounds__(256, 2)
void qconv_kernel(const float* __restrict__ rho_g,
                  const float* __restrict__ ux_g,
                  const float* __restrict__ uy_g,
                  const float* __restrict__ uc_g,
                  float* __restrict__ out_g)
{
    extern __shared__ float B[];  // [128][SROW]
    const int b = blockIdx.x;
    const int t = threadIdx.x;
    const float* rg = rho_g + (size_t)b * 16384;

    // ---- load rho[b] (128x128) into padded smem, coalesced float4 ----
    #pragma unroll
    for (int k = 0; k < 16; k++) {
        int e  = t + 256 * k;        // float4 index, 4096 total
        int r  = e >> 5;
        int c4 = e & 31;
        float4 v = *reinterpret_cast<const float4*>(rg + r * 128 + c4 * 4);
        *reinterpret_cast<float4*>(&B[r * SROW + c4 * 4]) = v;
    }

    float m[64];
    #pragma unroll
    for (int i = 0; i < 64; i++) m[i] = __ldg(uy_g + i);
    __syncthreads();

    // ---- step1: B[r, f*64+i*8+qj] = sum_j uy[qj,j] * B[r, f*64+i*8+j] ----
    #pragma unroll
    for (int k = 0; k < 8; k++) {
        int g = t + 256 * k;          // (r, f*8+i)
        int r = g >> 4;
        int h = g & 15;
        float* p = &B[r * SROW + h * 8];
        float4 v0 = *reinterpret_cast<float4*>(p);
        float4 v1 = *reinterpret_cast<float4*>(p + 4);
        float in[8] = {v0.x, v0.y, v0.z, v0.w, v1.x, v1.y, v1.z, v1.w};
        float acc[8];
        #pragma unroll
        for (int q = 0; q < 8; q++) {
            float s = 0.f;
            #pragma unroll
            for (int j = 0; j < 8; j++) s = fmaf(m[q * 8 + j], in[j], s);
            acc[q] = s;
        }
        *reinterpret_cast<float4*>(p)     = make_float4(acc[0], acc[1], acc[2], acc[3]);
        *reinterpret_cast<float4*>(p + 4) = make_float4(acc[4], acc[5], acc[6], acc[7]);
    }

    #pragma unroll
    for (int i = 0; i < 64; i++) m[i] = __ldg(ux_g + i);
    __syncthreads();

    // ---- step2: B[r, f*64+qi*8+qj] = sum_i ux[qi,i] * B[r, f*64+i*8+qj] ----
    #pragma unroll
    for (int k = 0; k < 8; k++) {
        int g  = t + 256 * k;         // (r, f*8+qj)
        int r  = g >> 4;
        int h  = g & 15;
        int fp = h >> 3;
        int qj = h & 7;
        float* p = &B[r * SROW + fp * 64 + qj];
        float in[8], acc[8];
        #pragma unroll
        for (int i = 0; i < 8; i++) in[i] = p[i * 8];
        #pragma unroll
        for (int q = 0; q < 8; q++) {
            float s = 0.f;
            #pragma unroll
            for (int i = 0; i < 8; i++) s = fmaf(m[q * 8 + i], in[i], s);
            acc[q] = s;
        }
        #pragma unroll
        for (int q = 0; q < 8; q++) p[q * 8] = acc[q];
    }

    #pragma unroll
    for (int i = 0; i < 64; i++) m[i] = __ldg(uy_g + i);
    __syncthreads();

    // ---- step3: B[f*64+i*8+qj, c] = sum_j uy[qj,j] * B[f*64+i*8+j, c] ----
    #pragma unroll
    for (int k = 0; k < 8; k++) {
        int task = t + 256 * k;       // (f*8+i, col)
        int col  = task & 127;
        int fi   = task >> 7;         // 0..15
        float* p = &B[fi * 8 * SROW + col];
        float in[8], acc[8];
        #pragma unroll
        for (int j = 0; j < 8; j++) in[j] = p[j * SROW];
        #pragma unroll
        for (int q = 0; q < 8; q++) {
            float s = 0.f;
            #pragma unroll
            for (int j = 0; j < 8; j++) s = fmaf(m[q * 8 + j], in[j], s);
            acc[q] = s;
        }
        #pragma unroll
        for (int q = 0; q < 8; q++) p[q * SROW] = acc[q];
    }

    #pragma unroll
    for (int i = 0; i < 64; i++) m[i] = __ldg(ux_g + i);
    __syncthreads();

    // ---- step4: B[f*64+qi*8+qj, c] = sum_i ux[qi,i] * B[f*64+i*8+qj, c] ----
    #pragma unroll
    for (int k = 0; k < 8; k++) {
        int task = t + 256 * k;       // (f*8+qj, col)
        int col  = task & 127;
        int fq   = task >> 7;
        int f    = fq >> 3;
        int qj   = fq & 7;
        float* p = &B[(f * 64 + qj) * SROW + col];
        float in[8], acc[8];
        #pragma unroll
        for (int i = 0; i < 8; i++) in[i] = p[i * 8 * SROW];
        #pragma unroll
        for (int q = 0; q < 8; q++) {
            float s = 0.f;
            #pragma unroll
            for (int i = 0; i < 8; i++) s = fmaf(m[q * 8 + i], in[i], s);
            acc[q] = s;
        }
        #pragma unroll
        for (int q = 0; q < 8; q++) p[q * 8 * SROW] = acc[q];
    }

    // ---- step5: out[c*64+p, c2*64+q] = sum_{f,f2} A[c][f] A[c2][f2] * B[f*64+p, f2*64+q]
    float A[4][2];
    #pragma unroll
    for (int c = 0; c < 4; c++) {
        A[c][0] = __ldg(uc_g + c * 4 + 2);
        A[c][1] = __ldg(uc_g + c * 4 + 3);
    }
    __syncthreads();

    float* og = out_g + (size_t)b * 65536;
    #pragma unroll
    for (int k = 0; k < 16; k++) {
        int e = t + 256 * k;          // 4096 (p,q) tasks
        int q = e & 63;
        int p = e >> 6;               // 0..63
        float s00 = B[p * SROW + q];
        float s01 = B[p * SROW + 64 + q];
        float s10 = B[(64 + p) * SROW + q];
        float s11 = B[(64 + p) * SROW + 64 + q];
        #pragma unroll
        for (int c = 0; c < 4; c++) {
            float t0 = fmaf(A[c][0], s00, A[c][1] * s10);
            float t1 = fmaf(A[c][0], s01, A[c][1] * s11);
            #pragma unroll
            for (int c2 = 0; c2 < 4; c2++) {
                og[(c * 64 + p) * 256 + c2 * 64 + q] =
                    fmaf(A[c2][0], t0, A[c2][1] * t1);
            }
        }
    }
}

extern "C" void kernel_launch(void* const* d_in, const int* in_sizes, int n_in,
                              void* d_out, int out_size)
{
    const float* rho = (const float*)d_in[0];
    const float* ux  = (const float*)d_in[1];
    const float* uy  = (const float*)d_in[2];
    const float* uc  = (const float*)d_in[3];
    float* out = (float*)d_out;

    const int smem_bytes = 128 * SROW * sizeof(float);  // 67584
    cudaFuncSetAttribute(qconv_kernel,
                         cudaFuncAttributeMaxDynamicSharedMemorySize, smem_bytes);
    qconv_kernel<<<256, 256, smem_bytes>>>(rho, ux, uy, uc, out);
}

// round 2
// speedup vs baseline: 1.1075x; 1.1075x over previous
#include <cuda_runtime.h>

// QConv2d: new_rho[b] = V * rho[b] * V^T, V = uc[:,2:4] (x) ux (x) uy.
// Mode-product formulation, one 128x132 f32 smem tile per batch, 256 blocks.
// Steps reordered (all four mode products commute):
//   P1: gmem load fused with j-col contraction (uy), write smem
//   P2: j-row contraction (uy, same registers)
//   P3: i-col contraction (ux)
//   P4: i-row contraction (ux)
//   P5: channel expansion with uc[:,2:4] both sides -> gmem (float4 stores)
// All 8-term contractions use packed fma.rn.f32x2 (4 FFMA2 + 1 FADD per output).

#define SROW 132
typedef unsigned long long ull;

__device__ __forceinline__ ull pk2(float lo, float hi) {
    ull r; asm("mov.b64 %0, {%1,%2};" : "=l"(r) : "f"(lo), "f"(hi)); return r;
}
__device__ __forceinline__ float2 upk(ull a) {
    float2 r; asm("mov.b64 {%0,%1}, %2;" : "=f"(r.x), "=f"(r.y) : "l"(a)); return r;
}
__device__ __forceinline__ ull ffma2(ull a, ull b, ull c) {
    ull d; asm("fma.rn.f32x2 %0, %1, %2, %3;" : "=l"(d) : "l"(a), "l"(b), "l"(c)); return d;
}
__device__ __forceinline__ ull fmul2(ull a, ull b) {
    ull d; asm("mul.rn.f32x2 %0, %1, %2;" : "=l"(d) : "l"(a), "l"(b)); return d;
}

// out[q] = sum_j m[q][j] * in[j], j-packed: m2[q*4+jp] = {m[q][2jp], m[q][2jp+1]}
__device__ __forceinline__ void contract8(const ull* m2, const ull* in2, float* out) {
    #pragma unroll
    for (int q = 0; q < 8; q++) {
        ull acc = fmul2(m2[q * 4 + 0], in2[0]);
        acc = ffma2(m2[q * 4 + 1], in2[1], acc);
        acc = ffma2(m2[q * 4 + 2], in2[2], acc);
        acc = ffma2(m2[q * 4 + 3], in2[3], acc);
        float2 a = upk(acc);
        out[q] = a.x + a.y;
    }
}

__global__ __launch_bounds__(256, 2)
void qconv_kernel(const float* __restrict__ rho_g,
                  const float* __restrict__ ux_g,
                  const float* __restrict__ uy_g,
                  const float* __restrict__ uc_g,
                  float* __restrict__ out_g)
{
    extern __shared__ float B[];  // [128][SROW]
    const int b = blockIdx.x;
    const int t = threadIdx.x;
    const float* rg = rho_g + (size_t)b * 16384;

    ull m2[32];
    const ull* uy2 = reinterpret_cast<const ull*>(uy_g);
    #pragma unroll
    for (int i = 0; i < 32; i++) m2[i] = __ldg(uy2 + i);

    // ---- P1: fused gmem load + j-col: B[r, f*64+i*8+q] = sum_j uy[q][j] rho[r, f*64+i*8+j]
    #pragma unroll
    for (int k = 0; k < 8; k++) {
        int g = t + 256 * k;          // (r, f*8+i)
        int r = g >> 4;
        int h = g & 15;
        const ulonglong2* src = reinterpret_cast<const ulonglong2*>(rg + r * 128 + h * 8);
        ulonglong2 v0 = __ldg(src);
        ulonglong2 v1 = __ldg(src + 1);
        ull in2[4] = {v0.x, v0.y, v1.x, v1.y};
        float o[8];
        contract8(m2, in2, o);
        float4* dst = reinterpret_cast<float4*>(&B[r * SROW + h * 8]);
        dst[0] = make_float4(o[0], o[1], o[2], o[3]);
        dst[1] = make_float4(o[4], o[5], o[6], o[7]);
    }
    __syncthreads();

    // ---- P2: j-row (uy still in regs): rows f*64+i*8+j down each column
    #pragma unroll
    for (int k = 0; k < 8; k++) {
        int task = t + 256 * k;       // (f*8+i, col)
        int col  = task & 127;
        int fi   = task >> 7;
        float* p = &B[fi * 8 * SROW + col];
        float s[8];
        #pragma unroll
        for (int j = 0; j < 8; j++) s[j] = p[j * SROW];
        ull in2[4] = {pk2(s[0], s[1]), pk2(s[2], s[3]), pk2(s[4], s[5]), pk2(s[6], s[7])};
        float o[8];
        contract8(m2, in2, o);
        #pragma unroll
        for (int q = 0; q < 8; q++) p[q * SROW] = o[q];
    }

    const ull* ux2 = reinterpret_cast<const ull*>(ux_g);
    #pragma unroll
    for (int i = 0; i < 32; i++) m2[i] = __ldg(ux2 + i);
    __syncthreads();

    // ---- P3: i-col: cols f*64+i*8+qj, stride 8
    #pragma unroll
    for (int k = 0; k < 8; k++) {
        int g  = t + 256 * k;         // (r, f*8+qj)
        int r  = g >> 4;
        int h  = g & 15;
        int fp = h >> 3;
        int qj = h & 7;
        float* p = &B[r * SROW + fp * 64 + qj];
        float s[8];
        #pragma unroll
        for (int i = 0; i < 8; i++) s[i] = p[i * 8];
        ull in2[4] = {pk2(s[0], s[1]), pk2(s[2], s[3]), pk2(s[4], s[5]), pk2(s[6], s[7])};
        float o[8];
        contract8(m2, in2, o);
        #pragma unroll
        for (int q = 0; q < 8; q++) p[q * 8] = o[q];
    }
    __syncthreads();

    // ---- P4: i-row: rows f*64+i*8+qj, stride 8*SROW
    #pragma unroll
    for (int k = 0; k < 8; k++) {
        int task = t + 256 * k;       // (f*8+qj, col)
        int col  = task & 127;
        int fq   = task >> 7;
        int f    = fq >> 3;
        int qj   = fq & 7;
        float* p = &B[(f * 64 + qj) * SROW + col];
        float s[8];
        #pragma unroll
        for (int i = 0; i < 8; i++) s[i] = p[i * 8 * SROW];
        ull in2[4] = {pk2(s[0], s[1]), pk2(s[2], s[3]), pk2(s[4], s[5]), pk2(s[6], s[7])};
        float o[8];
        contract8(m2, in2, o);
        #pragma unroll
        for (int q = 0; q < 8; q++) p[q * 8 * SROW] = o[q];
    }
    __syncthreads();

    // ---- P5: out[c*64+p, c2*64+q] = sum_{f,f2} A[c][f] A[c2][f2] B[f*64+p, f2*64+q]
    ull Ad0[4], Ad1[4];
    #pragma unroll
    for (int c = 0; c < 4; c++) {
        float a0 = __ldg(uc_g + c * 4 + 2);
        float a1 = __ldg(uc_g + c * 4 + 3);
        Ad0[c] = pk2(a0, a0);
        Ad1[c] = pk2(a1, a1);
    }

    float* og = out_g + (size_t)b * 65536;
    #pragma unroll
    for (int k = 0; k < 4; k++) {
        int e  = t + 256 * k;         // 1024 (p, q4) tasks
        int q4 = e & 15;
        int p  = e >> 4;              // 0..63
        ulonglong2 s00 = *reinterpret_cast<const ulonglong2*>(&B[p * SROW + q4 * 4]);
        ulonglong2 s01 = *reinterpret_cast<const ulonglong2*>(&B[p * SROW + 64 + q4 * 4]);
        ulonglong2 s10 = *reinterpret_cast<const ulonglong2*>(&B[(64 + p) * SROW + q4 * 4]);
        ulonglong2 s11 = *reinterpret_cast<const ulonglong2*>(&B[(64 + p) * SROW + 64 + q4 * 4]);
        #pragma unroll
        for (int c = 0; c < 4; c++) {
            ull t0a = ffma2(Ad0[c], s00.x, fmul2(Ad1[c], s10.x));
            ull t0b = ffma2(Ad0[c], s00.y, fmul2(Ad1[c], s10.y));
            ull t1a = ffma2(Ad0[c], s01.x, fmul2(Ad1[c], s11.x));
            ull t1b = ffma2(Ad0[c], s01.y, fmul2(Ad1[c], s11.y));
            #pragma unroll
            for (int c2 = 0; c2 < 4; c2++) {
                ull oa = ffma2(Ad0[c2], t0a, fmul2(Ad1[c2], t1a));
                ull ob = ffma2(Ad0[c2], t0b, fmul2(Ad1[c2], t1b));
                *reinterpret_cast<ulonglong2*>(og + (c * 64 + p) * 256 + c2 * 64 + q4 * 4) =
                    make_ulonglong2(oa, ob);
            }
        }
    }
}

extern "C" void kernel_launch(void* const* d_in, const int* in_sizes, int n_in,
                              void* d_out, int out_size)
{
    const float* rho = (const float*)d_in[0];
    const float* ux  = (const float*)d_in[1];
    const float* uy  = (const float*)d_in[2];
    const float* uc  = (const float*)d_in[3];
    float* out = (float*)d_out;

    const int smem_bytes = 128 * SROW * sizeof(float);  // 67584
    cudaFuncSetAttribute(qconv_kernel,
                         cudaFuncAttributeMaxDynamicSharedMemorySize, smem_bytes);
    qconv_kernel<<<256, 256, smem_bytes>>>(rho, ux, uy, uc, out);
}